// round 1
// baseline (speedup 1.0000x reference)
#include <cuda_runtime.h>
#include <cuda_bf16.h>
#include <cstdint>

// Problem constants (B=64, H=W=56, C=256, heads=8, hd=32, ws=7, shift=3)
#define IMG 56
#define CH 256
#define NHEAD 8
#define HD 32
#define WS 7
#define NWIN_SIDE 8              // 56/7
#define NWIN 64                  // 8*8 windows per image
#define NTOK 49                  // 7*7 tokens per window
#define BATCH 64
#define M_TOTAL (BATCH * IMG * IMG)   // 200704 tokens
#define QKV_N 768
#define QSCALE 0.17677669529663687f  // 1/sqrt(32)

// Scratch (device globals; allocation-free)
__device__ float g_qkv[(size_t)M_TOTAL * QKV_N];     // window-order [m, 768]
__device__ float g_attnout[(size_t)M_TOTAL * CH];    // window-order [m, 256]

// ---- index helpers ----------------------------------------------------
// window-order token m -> natural row in x ([B,56,56] flattened)
__device__ __forceinline__ int gather_src_row(int m) {
    int win = m / NTOK, n = m - win * NTOK;
    int b = win >> 6, wl = win & 63;
    int hr = (wl >> 3) * WS + n / WS;
    int wr = (wl & 7) * WS + n % WS;
    int h = hr + 3; if (h >= IMG) h -= IMG;   // roll(-3): rolled pos hr holds natural (hr+3)%56
    int w = wr + 3; if (w >= IMG) w -= IMG;
    return (b * IMG + h) * IMG + w;
}

// ---- GEMM: 128x128x8 tile, 256 threads, 8x8 per-thread ----------------
#define BM 128
#define BN 128
#define BK 8
#define TM 8
#define TN 8

// MODE 0: QKV gemm  (gather A rows, plain store to g_qkv, N=768)
// MODE 1: proj gemm (plain A rows from g_attnout, scatter store to d_out, N=256)
template <int MODE>
__global__ __launch_bounds__(256) void sgemm_kernel(
    const float* __restrict__ A,      // MODE0: x [200704,256]  MODE1: g_attnout
    const float* __restrict__ Bmat,   // [N, K] row-major (weight)
    const float* __restrict__ bias,   // [N]
    float* __restrict__ out)          // MODE0: g_qkv  MODE1: d_out
{
    const int K = CH;
    const int bm = blockIdx.y * BM;
    const int bn = blockIdx.x * BN;

    __shared__ float As[BK][BM];
    __shared__ float Bs[BK][BN];

    const int tid = threadIdx.x;
    const int ty = tid >> 4;          // 0..15
    const int tx = tid & 15;          // 0..15

    // A tile loader: row = tid/2 (0..127), 2 float4 per row along K
    const int arow = tid >> 1;
    const int acol4 = (tid & 1) * 4;
    int m_load = bm + arow;
    const float* Arow;
    if (MODE == 0) {
        Arow = A + (size_t)gather_src_row(m_load) * K;
    } else {
        Arow = A + (size_t)m_load * K;
    }
    const float* Brow = Bmat + (size_t)(bn + arow) * K;

    float acc[TM][TN];
#pragma unroll
    for (int i = 0; i < TM; i++)
#pragma unroll
        for (int j = 0; j < TN; j++) acc[i][j] = 0.f;

    for (int k0 = 0; k0 < K; k0 += BK) {
        float4 a4 = *(const float4*)(Arow + k0 + acol4);
        As[acol4 + 0][arow] = a4.x;
        As[acol4 + 1][arow] = a4.y;
        As[acol4 + 2][arow] = a4.z;
        As[acol4 + 3][arow] = a4.w;
        float4 b4 = *(const float4*)(Brow + k0 + acol4);
        Bs[acol4 + 0][arow] = b4.x;
        Bs[acol4 + 1][arow] = b4.y;
        Bs[acol4 + 2][arow] = b4.z;
        Bs[acol4 + 3][arow] = b4.w;
        __syncthreads();

#pragma unroll
        for (int k = 0; k < BK; k++) {
            float ra[TM], rb[TN];
#pragma unroll
            for (int i = 0; i < TM; i++) ra[i] = As[k][ty * TM + i];
#pragma unroll
            for (int j = 0; j < TN; j++) rb[j] = Bs[k][tx * TN + j];
#pragma unroll
            for (int i = 0; i < TM; i++)
#pragma unroll
                for (int j = 0; j < TN; j++) acc[i][j] = fmaf(ra[i], rb[j], acc[i][j]);
        }
        __syncthreads();
    }

    // epilogue: +bias, store
    const int ncol = bn + tx * TN;
    float4 bias0 = *(const float4*)(bias + ncol);
    float4 bias1 = *(const float4*)(bias + ncol + 4);

#pragma unroll
    for (int i = 0; i < TM; i++) {
        int m = bm + ty * TM + i;
        float* dst;
        if (MODE == 0) {
            dst = out + (size_t)m * QKV_N + ncol;
        } else {
            // scatter window-order row m back to natural layout (unpartition + roll(+3))
            dst = out + (size_t)gather_src_row(m) * CH + ncol;
        }
        float4 r0, r1;
        r0.x = acc[i][0] + bias0.x; r0.y = acc[i][1] + bias0.y;
        r0.z = acc[i][2] + bias0.z; r0.w = acc[i][3] + bias0.w;
        r1.x = acc[i][4] + bias1.x; r1.y = acc[i][5] + bias1.y;
        r1.z = acc[i][6] + bias1.z; r1.w = acc[i][7] + bias1.w;
        *(float4*)(dst)     = r0;
        *(float4*)(dst + 4) = r1;
    }
}

// ---- window attention: one CTA per (window, head) ---------------------
__global__ __launch_bounds__(128) void attn_kernel(
    const float* __restrict__ qkv,      // [4096*49, 768] window order
    const float* __restrict__ table,    // [169, 8]
    float* __restrict__ out)            // [4096*49, 256]
{
    const int blk = blockIdx.x;
    const int win = blk >> 3;
    const int head = blk & 7;
    const int tid = threadIdx.x;

    __shared__ float q[NTOK * HD];
    __shared__ float ksm[NTOK * HD];
    __shared__ float vsm[NTOK * HD];
    __shared__ float S[NTOK * NTOK];
    __shared__ int regid[NTOK];

    const float* base = qkv + (size_t)win * NTOK * QKV_N + head * HD;

    // load q (scaled), k, v : 49*32 floats each = 392 float4
    for (int i4 = tid; i4 < (NTOK * HD) / 4; i4 += 128) {
        int n = i4 >> 3;             // /8 float4 per row
        int d4 = (i4 & 7) * 4;
        const float* p = base + (size_t)n * QKV_N + d4;
        float4 a = *(const float4*)(p);
        a.x *= QSCALE; a.y *= QSCALE; a.z *= QSCALE; a.w *= QSCALE;
        *(float4*)(q + n * HD + d4) = a;
        *(float4*)(ksm + n * HD + d4) = *(const float4*)(p + 256);
        *(float4*)(vsm + n * HD + d4) = *(const float4*)(p + 512);
    }
    if (tid < NTOK) {
        int wl = win & 63;
        int hr = (wl >> 3) * WS + tid / WS;
        int wr = (wl & 7) * WS + tid % WS;
        int rh = (hr < 49) ? 0 : ((hr < 53) ? 1 : 2);
        int rw = (wr < 49) ? 0 : ((wr < 53) ? 1 : 2);
        regid[tid] = rh * 3 + rw;
    }
    __syncthreads();

    // S = q k^T + bias + mask
    for (int idx = tid; idx < NTOK * NTOK; idx += 128) {
        int i = idx / NTOK, j = idx - i * NTOK;
        const float* qi = q + i * HD;
        const float* kj = ksm + j * HD;
        float s = 0.f;
#pragma unroll
        for (int d = 0; d < HD; d += 4) {
            float4 qa = *(const float4*)(qi + d);
            float4 ka = *(const float4*)(kj + d);
            s = fmaf(qa.x, ka.x, s); s = fmaf(qa.y, ka.y, s);
            s = fmaf(qa.z, ka.z, s); s = fmaf(qa.w, ka.w, s);
        }
        int ih = i / WS, iw = i - ih * WS;
        int jh = j / WS, jw = j - jh * WS;
        int ridx = (ih - jh + 6) * 13 + (iw - jw + 6);
        s += __ldg(table + ridx * NHEAD + head);
        if (regid[i] != regid[j]) s -= 100.f;
        S[idx] = s;
    }
    __syncthreads();

    // softmax rows (one thread per row)
    if (tid < NTOK) {
        float* row = S + tid * NTOK;
        float mx = row[0];
#pragma unroll 8
        for (int j = 1; j < NTOK; j++) mx = fmaxf(mx, row[j]);
        float sum = 0.f;
#pragma unroll 8
        for (int j = 0; j < NTOK; j++) {
            float e = __expf(row[j] - mx);
            row[j] = e;
            sum += e;
        }
        float inv = 1.f / sum;
#pragma unroll 8
        for (int j = 0; j < NTOK; j++) row[j] *= inv;
    }
    __syncthreads();

    // O = S @ v  -> out[(win*49+n)*256 + head*32 + d]
    for (int idx = tid; idx < NTOK * HD; idx += 128) {
        int n = idx >> 5, d = idx & 31;
        const float* srow = S + n * NTOK;
        float s = 0.f;
#pragma unroll 7
        for (int m = 0; m < NTOK; m++) s = fmaf(srow[m], vsm[m * HD + d], s);
        out[((size_t)win * NTOK + n) * CH + head * HD + d] = s;
    }
}

extern "C" void kernel_launch(void* const* d_in, const int* in_sizes, int n_in,
                              void* d_out, int out_size) {
    const float* x      = (const float*)d_in[0];   // [64,56,56,256]
    const float* qkv_w  = (const float*)d_in[1];   // [768,256]
    const float* qkv_b  = (const float*)d_in[2];   // [768]
    const float* proj_w = (const float*)d_in[3];   // [256,256]
    const float* proj_b = (const float*)d_in[4];   // [256]
    const float* table  = (const float*)d_in[5];   // [169,8]
    float* out = (float*)d_out;

    float* qkv_buf;
    float* attn_buf;
    cudaGetSymbolAddress((void**)&qkv_buf, g_qkv);
    cudaGetSymbolAddress((void**)&attn_buf, g_attnout);

    // 1) QKV gemm with fused roll+window gather
    dim3 grid1(QKV_N / BN, M_TOTAL / BM);   // (6, 1568)
    sgemm_kernel<0><<<grid1, 256>>>(x, qkv_w, qkv_b, qkv_buf);

    // 2) window attention
    attn_kernel<<<BATCH * NWIN * NHEAD, 128>>>(qkv_buf, table, attn_buf);

    // 3) proj gemm with fused unpartition+roll scatter into d_out
    dim3 grid3(CH / BN, M_TOTAL / BM);      // (2, 1568)
    sgemm_kernel<1><<<grid3, 256>>>(attn_buf, proj_w, proj_b, out);
}

// round 3
// speedup vs baseline: 1.3169x; 1.3169x over previous
#include <cuda_runtime.h>
#include <cuda_bf16.h>
#include <cstdint>

// Problem constants (B=64, H=W=56, C=256, heads=8, hd=32, ws=7, shift=3)
#define IMG 56
#define CH 256
#define NHEAD 8
#define HD 32
#define WS 7
#define NWIN 64
#define NTOK 49
#define BATCH 64
#define M_TOTAL (BATCH * IMG * IMG)   // 200704
#define QKV_N 768
#define QSCALE 0.17677669529663687f

// Scratch
__device__ float g_qkv[(size_t)M_TOTAL * QKV_N];
__device__ float g_attnout[(size_t)M_TOTAL * CH];

// ---- index helper ------------------------------------------------------
__device__ __forceinline__ int gather_src_row(int m) {
    int win = m / NTOK, n = m - win * NTOK;
    int b = win >> 6, wl = win & 63;
    int hr = (wl >> 3) * WS + n / WS;
    int wr = (wl & 7) * WS + n % WS;
    int h = hr + 3; if (h >= IMG) h -= IMG;
    int w = wr + 3; if (w >= IMG) w -= IMG;
    return (b * IMG + h) * IMG + w;
}

// split a float pair into packed bf16x2 hi and lo
__device__ __forceinline__ void split_pack(float a, float b, uint32_t& hi, uint32_t& lo) {
    __nv_bfloat16 ha = __float2bfloat16_rn(a), hb = __float2bfloat16_rn(b);
    __nv_bfloat16 la = __float2bfloat16_rn(a - __bfloat162float(ha));
    __nv_bfloat16 lb = __float2bfloat16_rn(b - __bfloat162float(hb));
    __nv_bfloat162 h2; h2.x = ha; h2.y = hb;
    __nv_bfloat162 l2; l2.x = la; l2.y = lb;
    hi = *reinterpret_cast<uint32_t*>(&h2);
    lo = *reinterpret_cast<uint32_t*>(&l2);
}

__device__ __forceinline__ void mma16816(float* c,
    uint32_t a0, uint32_t a1, uint32_t a2, uint32_t a3,
    uint32_t b0, uint32_t b1) {
    asm volatile(
        "mma.sync.aligned.m16n8k16.row.col.f32.bf16.bf16.f32 "
        "{%0,%1,%2,%3}, {%4,%5,%6,%7}, {%8,%9}, {%0,%1,%2,%3};"
        : "+f"(c[0]), "+f"(c[1]), "+f"(c[2]), "+f"(c[3])
        : "r"(a0), "r"(a1), "r"(a2), "r"(a3), "r"(b0), "r"(b1));
}

// ---- HMMA GEMM: 128x128 tile, BK=32, double buffered -------------------
// MODE 0: QKV (gather A rows from x, out g_qkv stride 768)
// MODE 1: proj (A = g_attnout, scatter stores into d_out stride 256)
#define BK 32
#define SA 40                      // padded smem row stride (bf16 elems)
#define BUF_ELEMS (128 * SA)       // 5120 bf16 per matrix
#define BUF_BYTES (BUF_ELEMS * 2)  // 10240
#define STAGE_BYTES (4 * BUF_BYTES)        // Ahi|Alo|Bhi|Blo = 40960
#define SMEM_GEMM (2 * STAGE_BYTES)        // 81920

template <int MODE>
__global__ void __launch_bounds__(256, 1) tc_gemm(
    const float* __restrict__ A, const float* __restrict__ W,
    const float* __restrict__ bias, float* __restrict__ out)
{
    extern __shared__ __nv_bfloat16 sm[];
    const int tid = threadIdx.x;
    const int wid = tid >> 5;
    const int lane = tid & 31;
    const int gid = lane >> 2;       // 0..7
    const int t4 = lane & 3;         // 0..3
    const int wm = wid & 3;          // row group: 4 x 32
    const int wn = wid >> 2;         // col group: 2 x 64
    const int bm = blockIdx.y * 128;
    const int bn = blockIdx.x * 128;
    const int OUT_STRIDE = (MODE == 0) ? QKV_N : CH;

    // gmem loader geometry: row = tid>>1 (0..127), k half = (tid&1)*16
    const int lrow = tid >> 1;
    const int lk = (tid & 1) * 16;
    const float* Arow = (MODE == 0)
        ? (A + (size_t)gather_src_row(bm + lrow) * CH)
        : (A + (size_t)(bm + lrow) * CH);
    const float* Brow = W + (size_t)(bn + lrow) * CH;

    float acc[2][8][4];
#pragma unroll
    for (int mt = 0; mt < 2; mt++)
#pragma unroll
        for (int nt = 0; nt < 8; nt++)
#pragma unroll
            for (int r = 0; r < 4; r++) acc[mt][nt][r] = 0.f;

    // smem buffer pointers (bf16 elements)
    auto bufA_hi = [&](int st) { return sm + st * (STAGE_BYTES / 2); };
    auto bufA_lo = [&](int st) { return sm + st * (STAGE_BYTES / 2) + BUF_ELEMS; };
    auto bufB_hi = [&](int st) { return sm + st * (STAGE_BYTES / 2) + 2 * BUF_ELEMS; };
    auto bufB_lo = [&](int st) { return sm + st * (STAGE_BYTES / 2) + 3 * BUF_ELEMS; };

    // store one float4 (4 k values) as 4 bf16 into hi/lo buffers
    auto sts_split = [&](__nv_bfloat16* hi, __nv_bfloat16* lo, int k, float4 v) {
        uint32_t h0, l0, h1, l1;
        split_pack(v.x, v.y, h0, l0);
        split_pack(v.z, v.w, h1, l1);
        uint32_t* ph = (uint32_t*)(hi + lrow * SA + k);
        uint32_t* pl = (uint32_t*)(lo + lrow * SA + k);
        ph[0] = h0; ph[1] = h1;
        pl[0] = l0; pl[1] = l1;
    };

    // stage 0 load
    {
        float4 av[4], bv[4];
#pragma unroll
        for (int j = 0; j < 4; j++) {
            av[j] = *(const float4*)(Arow + lk + 4 * j);
            bv[j] = *(const float4*)(Brow + lk + 4 * j);
        }
#pragma unroll
        for (int j = 0; j < 4; j++) {
            sts_split(bufA_hi(0), bufA_lo(0), lk + 4 * j, av[j]);
            sts_split(bufB_hi(0), bufB_lo(0), lk + 4 * j, bv[j]);
        }
    }
    __syncthreads();

    const int NSTAGE = CH / BK;   // 8
    float4 av[4], bv[4];
    for (int s = 0; s < NSTAGE; s++) {
        const int p = s & 1;
        if (s + 1 < NSTAGE) {
            const int k0 = (s + 1) * BK;
#pragma unroll
            for (int j = 0; j < 4; j++) {
                av[j] = *(const float4*)(Arow + k0 + lk + 4 * j);
                bv[j] = *(const float4*)(Brow + k0 + lk + 4 * j);
            }
        }

        // compute on buffer p
        const __nv_bfloat16* Ah = bufA_hi(p);
        const __nv_bfloat16* Al = bufA_lo(p);
        const __nv_bfloat16* Bh = bufB_hi(p);
        const __nv_bfloat16* Bl = bufB_lo(p);
#pragma unroll
        for (int ksub = 0; ksub < 2; ksub++) {
            const int kk = ksub * 16 + 2 * t4;
            uint32_t ah[2][4], al[2][4];
#pragma unroll
            for (int mt = 0; mt < 2; mt++) {
                int r = wm * 32 + mt * 16 + gid;
                ah[mt][0] = *(const uint32_t*)(Ah + r * SA + kk);
                ah[mt][1] = *(const uint32_t*)(Ah + (r + 8) * SA + kk);
                ah[mt][2] = *(const uint32_t*)(Ah + r * SA + kk + 8);
                ah[mt][3] = *(const uint32_t*)(Ah + (r + 8) * SA + kk + 8);
                al[mt][0] = *(const uint32_t*)(Al + r * SA + kk);
                al[mt][1] = *(const uint32_t*)(Al + (r + 8) * SA + kk);
                al[mt][2] = *(const uint32_t*)(Al + r * SA + kk + 8);
                al[mt][3] = *(const uint32_t*)(Al + (r + 8) * SA + kk + 8);
            }
#pragma unroll
            for (int nt = 0; nt < 8; nt++) {
                int c = wn * 64 + nt * 8 + gid;
                uint32_t bh0 = *(const uint32_t*)(Bh + c * SA + kk);
                uint32_t bh1 = *(const uint32_t*)(Bh + c * SA + kk + 8);
                uint32_t bl0 = *(const uint32_t*)(Bl + c * SA + kk);
                uint32_t bl1 = *(const uint32_t*)(Bl + c * SA + kk + 8);
#pragma unroll
                for (int mt = 0; mt < 2; mt++) {
                    mma16816(acc[mt][nt], ah[mt][0], ah[mt][1], ah[mt][2], ah[mt][3], bh0, bh1);
                    mma16816(acc[mt][nt], ah[mt][0], ah[mt][1], ah[mt][2], ah[mt][3], bl0, bl1);
                    mma16816(acc[mt][nt], al[mt][0], al[mt][1], al[mt][2], al[mt][3], bh0, bh1);
                }
            }
        }
        __syncthreads();
        if (s + 1 < NSTAGE) {
            const int q = (s + 1) & 1;
            const int k0 = (s + 1) * BK;
            (void)k0;
#pragma unroll
            for (int j = 0; j < 4; j++) {
                sts_split(bufA_hi(q), bufA_lo(q), lk + 4 * j, av[j]);
                sts_split(bufB_hi(q), bufB_lo(q), lk + 4 * j, bv[j]);
            }
            __syncthreads();
        }
    }

    // epilogue: acc[mt][nt] rows (gid, gid+8), cols 2*t4, 2*t4+1
#pragma unroll
    for (int mt = 0; mt < 2; mt++) {
        int m1 = bm + wm * 32 + mt * 16 + gid;
        int m2 = m1 + 8;
        float* d1;
        float* d2;
        if (MODE == 0) {
            d1 = out + (size_t)m1 * OUT_STRIDE;
            d2 = out + (size_t)m2 * OUT_STRIDE;
        } else {
            d1 = out + (size_t)gather_src_row(m1) * OUT_STRIDE;
            d2 = out + (size_t)gather_src_row(m2) * OUT_STRIDE;
        }
#pragma unroll
        for (int nt = 0; nt < 8; nt++) {
            int n = bn + wn * 64 + nt * 8 + 2 * t4;
            float2 bv2 = *(const float2*)(bias + n);
            float2 r1, r2;
            r1.x = acc[mt][nt][0] + bv2.x; r1.y = acc[mt][nt][1] + bv2.y;
            r2.x = acc[mt][nt][2] + bv2.x; r2.y = acc[mt][nt][3] + bv2.y;
            *(float2*)(d1 + n) = r1;
            *(float2*)(d2 + n) = r2;
        }
    }
}

// ---- window attention (unchanged) --------------------------------------
__global__ __launch_bounds__(128) void attn_kernel(
    const float* __restrict__ qkv, const float* __restrict__ table,
    float* __restrict__ out)
{
    const int blk = blockIdx.x;
    const int win = blk >> 3;
    const int head = blk & 7;
    const int tid = threadIdx.x;

    __shared__ float q[NTOK * HD];
    __shared__ float ksm[NTOK * HD];
    __shared__ float vsm[NTOK * HD];
    __shared__ float S[NTOK * NTOK];
    __shared__ int regid[NTOK];

    const float* base = qkv + (size_t)win * NTOK * QKV_N + head * HD;

    for (int i4 = tid; i4 < (NTOK * HD) / 4; i4 += 128) {
        int n = i4 >> 3;
        int d4 = (i4 & 7) * 4;
        const float* p = base + (size_t)n * QKV_N + d4;
        float4 a = *(const float4*)(p);
        a.x *= QSCALE; a.y *= QSCALE; a.z *= QSCALE; a.w *= QSCALE;
        *(float4*)(q + n * HD + d4) = a;
        *(float4*)(ksm + n * HD + d4) = *(const float4*)(p + 256);
        *(float4*)(vsm + n * HD + d4) = *(const float4*)(p + 512);
    }
    if (tid < NTOK) {
        int wl = win & 63;
        int hr = (wl >> 3) * WS + tid / WS;
        int wr = (wl & 7) * WS + tid % WS;
        int rh = (hr < 49) ? 0 : ((hr < 53) ? 1 : 2);
        int rw = (wr < 49) ? 0 : ((wr < 53) ? 1 : 2);
        regid[tid] = rh * 3 + rw;
    }
    __syncthreads();

    for (int idx = tid; idx < NTOK * NTOK; idx += 128) {
        int i = idx / NTOK, j = idx - i * NTOK;
        const float* qi = q + i * HD;
        const float* kj = ksm + j * HD;
        float s = 0.f;
#pragma unroll
        for (int d = 0; d < HD; d += 4) {
            float4 qa = *(const float4*)(qi + d);
            float4 ka = *(const float4*)(kj + d);
            s = fmaf(qa.x, ka.x, s); s = fmaf(qa.y, ka.y, s);
            s = fmaf(qa.z, ka.z, s); s = fmaf(qa.w, ka.w, s);
        }
        int ih = i / WS, iw = i - ih * WS;
        int jh = j / WS, jw = j - jh * WS;
        int ridx = (ih - jh + 6) * 13 + (iw - jw + 6);
        s += __ldg(table + ridx * NHEAD + head);
        if (regid[i] != regid[j]) s -= 100.f;
        S[idx] = s;
    }
    __syncthreads();

    if (tid < NTOK) {
        float* row = S + tid * NTOK;
        float mx = row[0];
#pragma unroll 8
        for (int j = 1; j < NTOK; j++) mx = fmaxf(mx, row[j]);
        float sum = 0.f;
#pragma unroll 8
        for (int j = 0; j < NTOK; j++) {
            float e = __expf(row[j] - mx);
            row[j] = e;
            sum += e;
        }
        float inv = 1.f / sum;
#pragma unroll 8
        for (int j = 0; j < NTOK; j++) row[j] *= inv;
    }
    __syncthreads();

    for (int idx = tid; idx < NTOK * HD; idx += 128) {
        int n = idx >> 5, d = idx & 31;
        const float* srow = S + n * NTOK;
        float s = 0.f;
#pragma unroll 7
        for (int m = 0; m < NTOK; m++) s = fmaf(srow[m], vsm[m * HD + d], s);
        out[((size_t)win * NTOK + n) * CH + head * HD + d] = s;
    }
}

extern "C" void kernel_launch(void* const* d_in, const int* in_sizes, int n_in,
                              void* d_out, int out_size) {
    const float* x      = (const float*)d_in[0];
    const float* qkv_w  = (const float*)d_in[1];
    const float* qkv_b  = (const float*)d_in[2];
    const float* proj_w = (const float*)d_in[3];
    const float* proj_b = (const float*)d_in[4];
    const float* table  = (const float*)d_in[5];
    float* out = (float*)d_out;

    float* qkv_buf;
    float* attn_buf;
    cudaGetSymbolAddress((void**)&qkv_buf, g_qkv);
    cudaGetSymbolAddress((void**)&attn_buf, g_attnout);

    cudaFuncSetAttribute(tc_gemm<0>, cudaFuncAttributeMaxDynamicSharedMemorySize, SMEM_GEMM);
    cudaFuncSetAttribute(tc_gemm<1>, cudaFuncAttributeMaxDynamicSharedMemorySize, SMEM_GEMM);

    dim3 g1(QKV_N / 128, M_TOTAL / 128);   // (6, 1568)
    tc_gemm<0><<<g1, 256, SMEM_GEMM>>>(x, qkv_w, qkv_b, qkv_buf);

    attn_kernel<<<BATCH * NWIN * NHEAD, 128>>>(qkv_buf, table, attn_buf);

    dim3 g3(CH / 128, M_TOTAL / 128);      // (2, 1568)
    tc_gemm<1><<<g3, 256, SMEM_GEMM>>>(attn_buf, proj_w, proj_b, out);
}

// round 4
// speedup vs baseline: 2.9385x; 2.2314x over previous
#include <cuda_runtime.h>
#include <cuda_bf16.h>
#include <cstdint>

// Problem constants (B=64, H=W=56, C=256, heads=8, hd=32, ws=7, shift=3)
#define IMG 56
#define CH 256
#define NHEAD 8
#define HD 32
#define WS 7
#define NWIN 64
#define NTOK 49
#define BATCH 64
#define M_TOTAL (BATCH * IMG * IMG)   // 200704
#define QKV_N 768
#define QSCALE 0.17677669529663687f

// Scratch
__device__ float g_qkv[(size_t)M_TOTAL * QKV_N];
__device__ float g_attnout[(size_t)M_TOTAL * CH];

// ---- index helper ------------------------------------------------------
__device__ __forceinline__ int gather_src_row(int m) {
    int win = m / NTOK, n = m - win * NTOK;
    int b = win >> 6, wl = win & 63;
    int hr = (wl >> 3) * WS + n / WS;
    int wr = (wl & 7) * WS + n % WS;
    int h = hr + 3; if (h >= IMG) h -= IMG;
    int w = wr + 3; if (w >= IMG) w -= IMG;
    return (b * IMG + h) * IMG + w;
}

// split a float pair into packed bf16x2 hi and lo
__device__ __forceinline__ void split_pack(float a, float b, uint32_t& hi, uint32_t& lo) {
    __nv_bfloat16 ha = __float2bfloat16_rn(a), hb = __float2bfloat16_rn(b);
    __nv_bfloat16 la = __float2bfloat16_rn(a - __bfloat162float(ha));
    __nv_bfloat16 lb = __float2bfloat16_rn(b - __bfloat162float(hb));
    __nv_bfloat162 h2; h2.x = ha; h2.y = hb;
    __nv_bfloat162 l2; l2.x = la; l2.y = lb;
    hi = *reinterpret_cast<uint32_t*>(&h2);
    lo = *reinterpret_cast<uint32_t*>(&l2);
}

__device__ __forceinline__ void mma16816(float* c,
    uint32_t a0, uint32_t a1, uint32_t a2, uint32_t a3,
    uint32_t b0, uint32_t b1) {
    asm volatile(
        "mma.sync.aligned.m16n8k16.row.col.f32.bf16.bf16.f32 "
        "{%0,%1,%2,%3}, {%4,%5,%6,%7}, {%8,%9}, {%0,%1,%2,%3};"
        : "+f"(c[0]), "+f"(c[1]), "+f"(c[2]), "+f"(c[3])
        : "r"(a0), "r"(a1), "r"(a2), "r"(a3), "r"(b0), "r"(b1));
}

// ---- HMMA GEMM: 128x128 tile, BK=32, double buffered -------------------
#define BK 32
#define SA 40
#define BUF_ELEMS (128 * SA)
#define BUF_BYTES (BUF_ELEMS * 2)
#define STAGE_BYTES (4 * BUF_BYTES)
#define SMEM_GEMM (2 * STAGE_BYTES)

template <int MODE>
__global__ void __launch_bounds__(256, 1) tc_gemm(
    const float* __restrict__ A, const float* __restrict__ W,
    const float* __restrict__ bias, float* __restrict__ out)
{
    extern __shared__ __nv_bfloat16 sm[];
    const int tid = threadIdx.x;
    const int wid = tid >> 5;
    const int lane = tid & 31;
    const int gid = lane >> 2;
    const int t4 = lane & 3;
    const int wm = wid & 3;
    const int wn = wid >> 2;
    const int bm = blockIdx.y * 128;
    const int bn = blockIdx.x * 128;
    const int OUT_STRIDE = (MODE == 0) ? QKV_N : CH;

    const int lrow = tid >> 1;
    const int lk = (tid & 1) * 16;
    const float* Arow = (MODE == 0)
        ? (A + (size_t)gather_src_row(bm + lrow) * CH)
        : (A + (size_t)(bm + lrow) * CH);
    const float* Brow = W + (size_t)(bn + lrow) * CH;

    float acc[2][8][4];
#pragma unroll
    for (int mt = 0; mt < 2; mt++)
#pragma unroll
        for (int nt = 0; nt < 8; nt++)
#pragma unroll
            for (int r = 0; r < 4; r++) acc[mt][nt][r] = 0.f;

    auto bufA_hi = [&](int st) { return sm + st * (STAGE_BYTES / 2); };
    auto bufA_lo = [&](int st) { return sm + st * (STAGE_BYTES / 2) + BUF_ELEMS; };
    auto bufB_hi = [&](int st) { return sm + st * (STAGE_BYTES / 2) + 2 * BUF_ELEMS; };
    auto bufB_lo = [&](int st) { return sm + st * (STAGE_BYTES / 2) + 3 * BUF_ELEMS; };

    auto sts_split = [&](__nv_bfloat16* hi, __nv_bfloat16* lo, int k, float4 v) {
        uint32_t h0, l0, h1, l1;
        split_pack(v.x, v.y, h0, l0);
        split_pack(v.z, v.w, h1, l1);
        uint32_t* ph = (uint32_t*)(hi + lrow * SA + k);
        uint32_t* pl = (uint32_t*)(lo + lrow * SA + k);
        ph[0] = h0; ph[1] = h1;
        pl[0] = l0; pl[1] = l1;
    };

    {
        float4 av[4], bv[4];
#pragma unroll
        for (int j = 0; j < 4; j++) {
            av[j] = *(const float4*)(Arow + lk + 4 * j);
            bv[j] = *(const float4*)(Brow + lk + 4 * j);
        }
#pragma unroll
        for (int j = 0; j < 4; j++) {
            sts_split(bufA_hi(0), bufA_lo(0), lk + 4 * j, av[j]);
            sts_split(bufB_hi(0), bufB_lo(0), lk + 4 * j, bv[j]);
        }
    }
    __syncthreads();

    const int NSTAGE = CH / BK;
    float4 av[4], bv[4];
    for (int s = 0; s < NSTAGE; s++) {
        const int p = s & 1;
        if (s + 1 < NSTAGE) {
            const int k0 = (s + 1) * BK;
#pragma unroll
            for (int j = 0; j < 4; j++) {
                av[j] = *(const float4*)(Arow + k0 + lk + 4 * j);
                bv[j] = *(const float4*)(Brow + k0 + lk + 4 * j);
            }
        }

        const __nv_bfloat16* Ah = bufA_hi(p);
        const __nv_bfloat16* Al = bufA_lo(p);
        const __nv_bfloat16* Bh = bufB_hi(p);
        const __nv_bfloat16* Bl = bufB_lo(p);
#pragma unroll
        for (int ksub = 0; ksub < 2; ksub++) {
            const int kk = ksub * 16 + 2 * t4;
            uint32_t ah[2][4], al[2][4];
#pragma unroll
            for (int mt = 0; mt < 2; mt++) {
                int r = wm * 32 + mt * 16 + gid;
                ah[mt][0] = *(const uint32_t*)(Ah + r * SA + kk);
                ah[mt][1] = *(const uint32_t*)(Ah + (r + 8) * SA + kk);
                ah[mt][2] = *(const uint32_t*)(Ah + r * SA + kk + 8);
                ah[mt][3] = *(const uint32_t*)(Ah + (r + 8) * SA + kk + 8);
                al[mt][0] = *(const uint32_t*)(Al + r * SA + kk);
                al[mt][1] = *(const uint32_t*)(Al + (r + 8) * SA + kk);
                al[mt][2] = *(const uint32_t*)(Al + r * SA + kk + 8);
                al[mt][3] = *(const uint32_t*)(Al + (r + 8) * SA + kk + 8);
            }
#pragma unroll
            for (int nt = 0; nt < 8; nt++) {
                int c = wn * 64 + nt * 8 + gid;
                uint32_t bh0 = *(const uint32_t*)(Bh + c * SA + kk);
                uint32_t bh1 = *(const uint32_t*)(Bh + c * SA + kk + 8);
                uint32_t bl0 = *(const uint32_t*)(Bl + c * SA + kk);
                uint32_t bl1 = *(const uint32_t*)(Bl + c * SA + kk + 8);
#pragma unroll
                for (int mt = 0; mt < 2; mt++) {
                    mma16816(acc[mt][nt], ah[mt][0], ah[mt][1], ah[mt][2], ah[mt][3], bh0, bh1);
                    mma16816(acc[mt][nt], ah[mt][0], ah[mt][1], ah[mt][2], ah[mt][3], bl0, bl1);
                    mma16816(acc[mt][nt], al[mt][0], al[mt][1], al[mt][2], al[mt][3], bh0, bh1);
                }
            }
        }
        __syncthreads();
        if (s + 1 < NSTAGE) {
            const int q = (s + 1) & 1;
#pragma unroll
            for (int j = 0; j < 4; j++) {
                sts_split(bufA_hi(q), bufA_lo(q), lk + 4 * j, av[j]);
                sts_split(bufB_hi(q), bufB_lo(q), lk + 4 * j, bv[j]);
            }
            __syncthreads();
        }
    }

#pragma unroll
    for (int mt = 0; mt < 2; mt++) {
        int m1 = bm + wm * 32 + mt * 16 + gid;
        int m2 = m1 + 8;
        float* d1;
        float* d2;
        if (MODE == 0) {
            d1 = out + (size_t)m1 * OUT_STRIDE;
            d2 = out + (size_t)m2 * OUT_STRIDE;
        } else {
            d1 = out + (size_t)gather_src_row(m1) * OUT_STRIDE;
            d2 = out + (size_t)gather_src_row(m2) * OUT_STRIDE;
        }
#pragma unroll
        for (int nt = 0; nt < 8; nt++) {
            int n = bn + wn * 64 + nt * 8 + 2 * t4;
            float2 bv2 = *(const float2*)(bias + n);
            float2 r1, r2;
            r1.x = acc[mt][nt][0] + bv2.x; r1.y = acc[mt][nt][1] + bv2.y;
            r2.x = acc[mt][nt][2] + bv2.x; r2.y = acc[mt][nt][3] + bv2.y;
            *(float2*)(d1 + n) = r1;
            *(float2*)(d2 + n) = r2;
        }
    }
}

// ---- HMMA window attention: one warp per (window, head) ----------------
// S = Q K^T (64x64, hi/lo split), in-register softmax, O = P V (hi/lo split)
__global__ void __launch_bounds__(32) attn_mma_kernel(
    const float* __restrict__ qkv, const float* __restrict__ table,
    float* __restrict__ out)
{
    const int blk = blockIdx.x;
    const int win = blk >> 3;
    const int head = blk & 7;
    const int lane = threadIdx.x;
    const int gid = lane >> 2;
    const int t4 = lane & 3;
    const int wl = win & 63;
    const int hbase = (wl >> 3) * WS;
    const int wbase = (wl & 7) * WS;

    // smem: b32 pair tiles (bf16x2 along k), padded strides
    __shared__ uint32_t QH[64 * 17], QL[64 * 17];
    __shared__ uint32_t KH[64 * 17], KL[64 * 17];
    __shared__ uint32_t VTH[32 * 33], VTL[32 * 33];
    __shared__ float VF[64 * 33];
    __shared__ float TBL[169];

    for (int t = lane; t < 169; t += 32) TBL[t] = table[t * NHEAD + head];

    // load q/k (split bf16) and v (fp32 staging)
    for (int r = lane; r < 64; r += 32) {
        bool valid = r < NTOK;
        const float* p = qkv + ((size_t)win * NTOK + (valid ? r : 0)) * QKV_N + head * HD;
#pragma unroll
        for (int j = 0; j < 8; j++) {
            float4 qv, kv, vv;
            if (valid) {
                qv = *(const float4*)(p + 4 * j);
                kv = *(const float4*)(p + 256 + 4 * j);
                vv = *(const float4*)(p + 512 + 4 * j);
            } else {
                qv = make_float4(0, 0, 0, 0); kv = qv; vv = qv;
            }
            qv.x *= QSCALE; qv.y *= QSCALE; qv.z *= QSCALE; qv.w *= QSCALE;
            uint32_t h0, l0, h1, l1;
            split_pack(qv.x, qv.y, h0, l0); split_pack(qv.z, qv.w, h1, l1);
            QH[r * 17 + 2 * j] = h0; QH[r * 17 + 2 * j + 1] = h1;
            QL[r * 17 + 2 * j] = l0; QL[r * 17 + 2 * j + 1] = l1;
            split_pack(kv.x, kv.y, h0, l0); split_pack(kv.z, kv.w, h1, l1);
            KH[r * 17 + 2 * j] = h0; KH[r * 17 + 2 * j + 1] = h1;
            KL[r * 17 + 2 * j] = l0; KL[r * 17 + 2 * j + 1] = l1;
            VF[r * 33 + 4 * j + 0] = vv.x; VF[r * 33 + 4 * j + 1] = vv.y;
            VF[r * 33 + 4 * j + 2] = vv.z; VF[r * 33 + 4 * j + 3] = vv.w;
        }
    }
    __syncwarp();

    // transpose v: VT[d][token-pair] (lane = d, conflict-free)
#pragma unroll 4
    for (int tp = 0; tp < 32; tp++) {
        float a = VF[(2 * tp) * 33 + lane];
        float b = VF[(2 * tp + 1) * 33 + lane];
        uint32_t h, l; split_pack(a, b, h, l);
        VTH[lane * 33 + tp] = h; VTL[lane * 33 + tp] = l;
    }
    __syncwarp();

    float o[4][4][4];
#pragma unroll
    for (int a = 0; a < 4; a++)
#pragma unroll
        for (int b = 0; b < 4; b++)
#pragma unroll
            for (int r = 0; r < 4; r++) o[a][b][r] = 0.f;

#pragma unroll
    for (int mt = 0; mt < 4; mt++) {
        const int r0 = mt * 16 + gid;
        // Q A-fragments
        uint32_t qh[2][4], ql[2][4];
#pragma unroll
        for (int ks = 0; ks < 2; ks++) {
            int cp = ks * 8 + t4;
            qh[ks][0] = QH[r0 * 17 + cp];       qh[ks][1] = QH[(r0 + 8) * 17 + cp];
            qh[ks][2] = QH[r0 * 17 + cp + 4];   qh[ks][3] = QH[(r0 + 8) * 17 + cp + 4];
            ql[ks][0] = QL[r0 * 17 + cp];       ql[ks][1] = QL[(r0 + 8) * 17 + cp];
            ql[ks][2] = QL[r0 * 17 + cp + 4];   ql[ks][3] = QL[(r0 + 8) * 17 + cp + 4];
        }
        float c[8][4];
#pragma unroll
        for (int nt = 0; nt < 8; nt++) { c[nt][0] = c[nt][1] = c[nt][2] = c[nt][3] = 0.f; }
#pragma unroll
        for (int nt = 0; nt < 8; nt++) {
            int cn = nt * 8 + gid;
#pragma unroll
            for (int ks = 0; ks < 2; ks++) {
                int cp = ks * 8 + t4;
                uint32_t bh0 = KH[cn * 17 + cp], bh1 = KH[cn * 17 + cp + 4];
                uint32_t bl0 = KL[cn * 17 + cp], bl1 = KL[cn * 17 + cp + 4];
                mma16816(c[nt], qh[ks][0], qh[ks][1], qh[ks][2], qh[ks][3], bh0, bh1);
                mma16816(c[nt], qh[ks][0], qh[ks][1], qh[ks][2], qh[ks][3], bl0, bl1);
                mma16816(c[nt], ql[ks][0], ql[ks][1], ql[ks][2], ql[ks][3], bh0, bh1);
            }
        }

        // bias + shift mask + padding mask
        const int i0 = r0, i1 = r0 + 8;
        const int ii0 = min(i0, NTOK - 1), ii1 = min(i1, NTOK - 1);
        const int ih0 = ii0 / WS, iw0 = ii0 % WS;
        const int ih1 = ii1 / WS, iw1 = ii1 % WS;
        int hr, wr, rh, rw;
        hr = hbase + ih0; wr = wbase + iw0;
        rh = (hr < 49) ? 0 : ((hr < 53) ? 1 : 2); rw = (wr < 49) ? 0 : ((wr < 53) ? 1 : 2);
        const int rg0 = rh * 3 + rw;
        hr = hbase + ih1; wr = wbase + iw1;
        rh = (hr < 49) ? 0 : ((hr < 53) ? 1 : 2); rw = (wr < 49) ? 0 : ((wr < 53) ? 1 : 2);
        const int rg1 = rh * 3 + rw;

#pragma unroll
        for (int nt = 0; nt < 8; nt++) {
#pragma unroll
            for (int jc = 0; jc < 2; jc++) {
                int j = nt * 8 + 2 * t4 + jc;
                if (j < NTOK) {
                    int jh = j / WS, jw = j % WS;
                    int jhr = hbase + jh, jwr = wbase + jw;
                    int rjh = (jhr < 49) ? 0 : ((jhr < 53) ? 1 : 2);
                    int rjw = (jwr < 49) ? 0 : ((jwr < 53) ? 1 : 2);
                    int rgj = rjh * 3 + rjw;
                    float b0 = TBL[(ih0 - jh + 6) * 13 + (iw0 - jw + 6)];
                    float b1 = TBL[(ih1 - jh + 6) * 13 + (iw1 - jw + 6)];
                    if (rg0 != rgj) b0 -= 100.f;
                    if (rg1 != rgj) b1 -= 100.f;
                    c[nt][jc] += b0;
                    c[nt][2 + jc] += b1;
                } else {
                    c[nt][jc] = -1e30f;
                    c[nt][2 + jc] = -1e30f;
                }
            }
        }

        // softmax (rows i0 -> c[*][0,1], i1 -> c[*][2,3]), reduce over t4 quad
        float m0 = -1e30f, m1 = -1e30f;
#pragma unroll
        for (int nt = 0; nt < 8; nt++) {
            m0 = fmaxf(m0, fmaxf(c[nt][0], c[nt][1]));
            m1 = fmaxf(m1, fmaxf(c[nt][2], c[nt][3]));
        }
        m0 = fmaxf(m0, __shfl_xor_sync(0xffffffffu, m0, 1));
        m0 = fmaxf(m0, __shfl_xor_sync(0xffffffffu, m0, 2));
        m1 = fmaxf(m1, __shfl_xor_sync(0xffffffffu, m1, 1));
        m1 = fmaxf(m1, __shfl_xor_sync(0xffffffffu, m1, 2));
        float s0 = 0.f, s1 = 0.f;
#pragma unroll
        for (int nt = 0; nt < 8; nt++) {
            c[nt][0] = __expf(c[nt][0] - m0); s0 += c[nt][0];
            c[nt][1] = __expf(c[nt][1] - m0); s0 += c[nt][1];
            c[nt][2] = __expf(c[nt][2] - m1); s1 += c[nt][2];
            c[nt][3] = __expf(c[nt][3] - m1); s1 += c[nt][3];
        }
        s0 += __shfl_xor_sync(0xffffffffu, s0, 1);
        s0 += __shfl_xor_sync(0xffffffffu, s0, 2);
        s1 += __shfl_xor_sync(0xffffffffu, s1, 1);
        s1 += __shfl_xor_sync(0xffffffffu, s1, 2);
        const float inv0 = 1.f / s0, inv1 = 1.f / s1;
#pragma unroll
        for (int nt = 0; nt < 8; nt++) {
            c[nt][0] *= inv0; c[nt][1] *= inv0;
            c[nt][2] *= inv1; c[nt][3] *= inv1;
        }

        // O += P V : P A-frags pack directly from C regs (layouts coincide)
#pragma unroll
        for (int kt = 0; kt < 4; kt++) {
            uint32_t ph[4], pl[4];
            split_pack(c[2 * kt][0],     c[2 * kt][1],     ph[0], pl[0]);
            split_pack(c[2 * kt][2],     c[2 * kt][3],     ph[1], pl[1]);
            split_pack(c[2 * kt + 1][0], c[2 * kt + 1][1], ph[2], pl[2]);
            split_pack(c[2 * kt + 1][2], c[2 * kt + 1][3], ph[3], pl[3]);
#pragma unroll
            for (int nt = 0; nt < 4; nt++) {
                int dn = nt * 8 + gid;
                uint32_t bh0 = VTH[dn * 33 + kt * 8 + t4];
                uint32_t bh1 = VTH[dn * 33 + kt * 8 + t4 + 4];
                uint32_t bl0 = VTL[dn * 33 + kt * 8 + t4];
                uint32_t bl1 = VTL[dn * 33 + kt * 8 + t4 + 4];
                mma16816(o[mt][nt], ph[0], ph[1], ph[2], ph[3], bh0, bh1);
                mma16816(o[mt][nt], ph[0], ph[1], ph[2], ph[3], bl0, bl1);
                mma16816(o[mt][nt], pl[0], pl[1], pl[2], pl[3], bh0, bh1);
            }
        }
    }

    // store O
#pragma unroll
    for (int mt = 0; mt < 4; mt++) {
        int i0 = mt * 16 + gid, i1 = i0 + 8;
#pragma unroll
        for (int nt = 0; nt < 4; nt++) {
            int d = nt * 8 + 2 * t4;
            if (i0 < NTOK) {
                float2 r; r.x = o[mt][nt][0]; r.y = o[mt][nt][1];
                *(float2*)(out + ((size_t)win * NTOK + i0) * CH + head * HD + d) = r;
            }
            if (i1 < NTOK) {
                float2 r; r.x = o[mt][nt][2]; r.y = o[mt][nt][3];
                *(float2*)(out + ((size_t)win * NTOK + i1) * CH + head * HD + d) = r;
            }
        }
    }
}

extern "C" void kernel_launch(void* const* d_in, const int* in_sizes, int n_in,
                              void* d_out, int out_size) {
    const float* x      = (const float*)d_in[0];
    const float* qkv_w  = (const float*)d_in[1];
    const float* qkv_b  = (const float*)d_in[2];
    const float* proj_w = (const float*)d_in[3];
    const float* proj_b = (const float*)d_in[4];
    const float* table  = (const float*)d_in[5];
    float* out = (float*)d_out;

    float* qkv_buf;
    float* attn_buf;
    cudaGetSymbolAddress((void**)&qkv_buf, g_qkv);
    cudaGetSymbolAddress((void**)&attn_buf, g_attnout);

    cudaFuncSetAttribute(tc_gemm<0>, cudaFuncAttributeMaxDynamicSharedMemorySize, SMEM_GEMM);
    cudaFuncSetAttribute(tc_gemm<1>, cudaFuncAttributeMaxDynamicSharedMemorySize, SMEM_GEMM);

    dim3 g1(QKV_N / 128, M_TOTAL / 128);   // (6, 1568)
    tc_gemm<0><<<g1, 256, SMEM_GEMM>>>(x, qkv_w, qkv_b, qkv_buf);

    attn_mma_kernel<<<BATCH * NWIN * NHEAD, 32>>>(qkv_buf, table, attn_buf);

    dim3 g3(CH / 128, M_TOTAL / 128);      // (2, 1568)
    tc_gemm<1><<<g3, 256, SMEM_GEMM>>>(attn_buf, proj_w, proj_b, out);
}

// round 5
// speedup vs baseline: 3.7358x; 1.2713x over previous
#include <cuda_runtime.h>
#include <cuda_bf16.h>
#include <cstdint>

// Problem constants (B=64, H=W=56, C=256, heads=8, hd=32, ws=7, shift=3)
#define IMG 56
#define CH 256
#define NHEAD 8
#define HD 32
#define WS 7
#define NWIN 64
#define NTOK 49
#define BATCH 64
#define M_TOTAL (BATCH * IMG * IMG)   // 200704
#define QKV_N 768
#define QSCALE 0.17677669529663687f

// Scratch
__device__ float g_qkv[(size_t)M_TOTAL * QKV_N];
__device__ float g_attnout[(size_t)M_TOTAL * CH];

// ---- index helper ------------------------------------------------------
__device__ __forceinline__ int gather_src_row(int m) {
    int win = m / NTOK, n = m - win * NTOK;
    int b = win >> 6, wl = win & 63;
    int hr = (wl >> 3) * WS + n / WS;
    int wr = (wl & 7) * WS + n % WS;
    int h = hr + 3; if (h >= IMG) h -= IMG;
    int w = wr + 3; if (w >= IMG) w -= IMG;
    return (b * IMG + h) * IMG + w;
}

// split a float pair into packed bf16x2 hi and lo
__device__ __forceinline__ void split_pack(float a, float b, uint32_t& hi, uint32_t& lo) {
    __nv_bfloat16 ha = __float2bfloat16_rn(a), hb = __float2bfloat16_rn(b);
    __nv_bfloat16 la = __float2bfloat16_rn(a - __bfloat162float(ha));
    __nv_bfloat16 lb = __float2bfloat16_rn(b - __bfloat162float(hb));
    __nv_bfloat162 h2; h2.x = ha; h2.y = hb;
    __nv_bfloat162 l2; l2.x = la; l2.y = lb;
    hi = *reinterpret_cast<uint32_t*>(&h2);
    lo = *reinterpret_cast<uint32_t*>(&l2);
}

__device__ __forceinline__ void mma16816(float* c,
    uint32_t a0, uint32_t a1, uint32_t a2, uint32_t a3,
    uint32_t b0, uint32_t b1) {
    asm volatile(
        "mma.sync.aligned.m16n8k16.row.col.f32.bf16.bf16.f32 "
        "{%0,%1,%2,%3}, {%4,%5,%6,%7}, {%8,%9}, {%0,%1,%2,%3};"
        : "+f"(c[0]), "+f"(c[1]), "+f"(c[2]), "+f"(c[3])
        : "r"(a0), "r"(a1), "r"(a2), "r"(a3), "r"(b0), "r"(b1));
}

// ---- HMMA GEMM: 128x256 tile, 512 threads (16 warps of 32x64), BK=32 ---
#define BK 32
#define SA 40
#define A_ELEMS (128 * SA)                 // 5120 bf16
#define B_ELEMS (256 * SA)                 // 10240 bf16
#define STG (2 * A_ELEMS + 2 * B_ELEMS)    // 30720 bf16 per stage
#define SMEM_GEMM (2 * STG * 2)            // 122880 bytes

template <int MODE>
__global__ void __launch_bounds__(512, 1) tc_gemm(
    const float* __restrict__ A, const float* __restrict__ W,
    const float* __restrict__ bias, float* __restrict__ out)
{
    extern __shared__ __nv_bfloat16 sm[];
    const int tid = threadIdx.x;
    const int wid = tid >> 5;
    const int lane = tid & 31;
    const int gid = lane >> 2;
    const int t4 = lane & 3;
    const int wm = wid & 3;          // 4 row groups of 32
    const int wn = wid >> 2;         // 4 col groups of 64
    const int bm = blockIdx.y * 128;
    const int bn = blockIdx.x * 256;
    const int OUT_STRIDE = (MODE == 0) ? QKV_N : CH;

    // loaders: A row = tid>>2 (0..127), 8 k's; B row = tid>>1 (0..255), 16 k's
    const int arow = tid >> 2;
    const int ak = (tid & 3) * 8;
    const int brow = tid >> 1;
    const int bk = (tid & 1) * 16;
    const float* Arow = (MODE == 0)
        ? (A + (size_t)gather_src_row(bm + arow) * CH)
        : (A + (size_t)(bm + arow) * CH);
    const float* Brow = W + (size_t)(bn + brow) * CH;

    float acc[2][8][4];
#pragma unroll
    for (int mt = 0; mt < 2; mt++)
#pragma unroll
        for (int nt = 0; nt < 8; nt++)
#pragma unroll
            for (int r = 0; r < 4; r++) acc[mt][nt][r] = 0.f;

    auto Ahi = [&](int st) { return sm + st * STG; };
    auto Alo = [&](int st) { return sm + st * STG + A_ELEMS; };
    auto Bhi = [&](int st) { return sm + st * STG + 2 * A_ELEMS; };
    auto Blo = [&](int st) { return sm + st * STG + 2 * A_ELEMS + B_ELEMS; };

    auto sts_stage = [&](int st, const float4* av, const float4* bv) {
        uint32_t h0, l0, h1, l1;
        uint32_t* ph = (uint32_t*)(Ahi(st) + arow * SA + ak);
        uint32_t* pl = (uint32_t*)(Alo(st) + arow * SA + ak);
        split_pack(av[0].x, av[0].y, h0, l0); ph[0] = h0; pl[0] = l0;
        split_pack(av[0].z, av[0].w, h1, l1); ph[1] = h1; pl[1] = l1;
        split_pack(av[1].x, av[1].y, h0, l0); ph[2] = h0; pl[2] = l0;
        split_pack(av[1].z, av[1].w, h1, l1); ph[3] = h1; pl[3] = l1;
        uint32_t* qh = (uint32_t*)(Bhi(st) + brow * SA + bk);
        uint32_t* ql = (uint32_t*)(Blo(st) + brow * SA + bk);
#pragma unroll
        for (int j = 0; j < 4; j++) {
            split_pack(bv[j].x, bv[j].y, h0, l0); qh[2 * j] = h0; ql[2 * j] = l0;
            split_pack(bv[j].z, bv[j].w, h1, l1); qh[2 * j + 1] = h1; ql[2 * j + 1] = l1;
        }
    };

    float4 av[2], bv[4];
    // stage 0
    av[0] = *(const float4*)(Arow + ak);
    av[1] = *(const float4*)(Arow + ak + 4);
#pragma unroll
    for (int j = 0; j < 4; j++) bv[j] = *(const float4*)(Brow + bk + 4 * j);
    sts_stage(0, av, bv);
    __syncthreads();

    const int NSTAGE = CH / BK;   // 8
    for (int s = 0; s < NSTAGE; s++) {
        const int p = s & 1;
        if (s + 1 < NSTAGE) {
            const int k0 = (s + 1) * BK;
            av[0] = *(const float4*)(Arow + k0 + ak);
            av[1] = *(const float4*)(Arow + k0 + ak + 4);
#pragma unroll
            for (int j = 0; j < 4; j++) bv[j] = *(const float4*)(Brow + k0 + bk + 4 * j);
        }

        const __nv_bfloat16* Ah = Ahi(p);
        const __nv_bfloat16* Al = Alo(p);
        const __nv_bfloat16* Bh = Bhi(p);
        const __nv_bfloat16* Bl = Blo(p);
#pragma unroll
        for (int ksub = 0; ksub < 2; ksub++) {
            const int kk = ksub * 16 + 2 * t4;
            uint32_t ah[2][4], al[2][4];
#pragma unroll
            for (int mt = 0; mt < 2; mt++) {
                int r = wm * 32 + mt * 16 + gid;
                ah[mt][0] = *(const uint32_t*)(Ah + r * SA + kk);
                ah[mt][1] = *(const uint32_t*)(Ah + (r + 8) * SA + kk);
                ah[mt][2] = *(const uint32_t*)(Ah + r * SA + kk + 8);
                ah[mt][3] = *(const uint32_t*)(Ah + (r + 8) * SA + kk + 8);
                al[mt][0] = *(const uint32_t*)(Al + r * SA + kk);
                al[mt][1] = *(const uint32_t*)(Al + (r + 8) * SA + kk);
                al[mt][2] = *(const uint32_t*)(Al + r * SA + kk + 8);
                al[mt][3] = *(const uint32_t*)(Al + (r + 8) * SA + kk + 8);
            }
#pragma unroll
            for (int nt = 0; nt < 8; nt++) {
                int c = wn * 64 + nt * 8 + gid;
                uint32_t bh0 = *(const uint32_t*)(Bh + c * SA + kk);
                uint32_t bh1 = *(const uint32_t*)(Bh + c * SA + kk + 8);
                uint32_t bl0 = *(const uint32_t*)(Bl + c * SA + kk);
                uint32_t bl1 = *(const uint32_t*)(Bl + c * SA + kk + 8);
#pragma unroll
                for (int mt = 0; mt < 2; mt++) {
                    mma16816(acc[mt][nt], ah[mt][0], ah[mt][1], ah[mt][2], ah[mt][3], bh0, bh1);
                    mma16816(acc[mt][nt], ah[mt][0], ah[mt][1], ah[mt][2], ah[mt][3], bl0, bl1);
                    mma16816(acc[mt][nt], al[mt][0], al[mt][1], al[mt][2], al[mt][3], bh0, bh1);
                }
            }
        }
        __syncthreads();
        if (s + 1 < NSTAGE) {
            sts_stage((s + 1) & 1, av, bv);
            __syncthreads();
        }
    }

#pragma unroll
    for (int mt = 0; mt < 2; mt++) {
        int m1 = bm + wm * 32 + mt * 16 + gid;
        int m2 = m1 + 8;
        float* d1;
        float* d2;
        if (MODE == 0) {
            d1 = out + (size_t)m1 * OUT_STRIDE;
            d2 = out + (size_t)m2 * OUT_STRIDE;
        } else {
            d1 = out + (size_t)gather_src_row(m1) * OUT_STRIDE;
            d2 = out + (size_t)gather_src_row(m2) * OUT_STRIDE;
        }
#pragma unroll
        for (int nt = 0; nt < 8; nt++) {
            int n = bn + wn * 64 + nt * 8 + 2 * t4;
            float2 bv2 = *(const float2*)(bias + n);
            float2 r1, r2;
            r1.x = acc[mt][nt][0] + bv2.x; r1.y = acc[mt][nt][1] + bv2.y;
            r2.x = acc[mt][nt][2] + bv2.x; r2.y = acc[mt][nt][3] + bv2.y;
            *(float2*)(d1 + n) = r1;
            *(float2*)(d2 + n) = r2;
        }
    }
}

// ---- HMMA window attention: one warp per (window, head), lean smem -----
__global__ void __launch_bounds__(32) attn_mma_kernel(
    const float* __restrict__ qkv, const float* __restrict__ table,
    float* __restrict__ out)
{
    const int blk = blockIdx.x;
    const int win = blk >> 3;
    const int head = blk & 7;
    const int lane = threadIdx.x;
    const int gid = lane >> 2;
    const int t4 = lane & 3;
    const int wl = win & 63;
    const int hbase = (wl >> 3) * WS;
    const int wbase = (wl & 7) * WS;

    __shared__ uint32_t KH[64 * 17], KL[64 * 17];
    __shared__ uint32_t VTH[32 * 33], VTL[32 * 33];
    __shared__ float TBL[169];

    for (int t = lane; t < 169; t += 32) TBL[t] = table[t * NHEAD + head];

    const float* base = qkv + (size_t)win * NTOK * QKV_N + head * HD;

    // K: cooperative coalesced load, split bf16, zero padding rows
    for (int r = lane; r < 64; r += 32) {
        bool valid = r < NTOK;
        const float* p = base + (size_t)(valid ? r : 0) * QKV_N + 256;
#pragma unroll
        for (int j = 0; j < 8; j++) {
            float4 kv = valid ? *(const float4*)(p + 4 * j) : make_float4(0, 0, 0, 0);
            uint32_t h0, l0, h1, l1;
            split_pack(kv.x, kv.y, h0, l0); split_pack(kv.z, kv.w, h1, l1);
            KH[r * 17 + 2 * j] = h0; KH[r * 17 + 2 * j + 1] = h1;
            KL[r * 17 + 2 * j] = l0; KL[r * 17 + 2 * j + 1] = l1;
        }
    }

    // V transposed directly from gmem: lane = d, coalesced per token
    const float* vbase = base + 512;
#pragma unroll 4
    for (int tp = 0; tp < 32; tp++) {
        int t0 = 2 * tp, t1 = 2 * tp + 1;
        float a = (t0 < NTOK) ? vbase[(size_t)t0 * QKV_N + lane] : 0.f;
        float b = (t1 < NTOK) ? vbase[(size_t)t1 * QKV_N + lane] : 0.f;
        uint32_t h, l; split_pack(a, b, h, l);
        VTH[lane * 33 + tp] = h; VTL[lane * 33 + tp] = l;
    }
    __syncwarp();

    float o[4][4][4];
#pragma unroll
    for (int a = 0; a < 4; a++)
#pragma unroll
        for (int b = 0; b < 4; b++)
#pragma unroll
            for (int r = 0; r < 4; r++) o[a][b][r] = 0.f;

#pragma unroll
    for (int mt = 0; mt < 4; mt++) {
        const int r0 = mt * 16 + gid;
        const int rc0 = min(r0, NTOK - 1);
        const int rc1 = min(r0 + 8, NTOK - 1);
        const float* q0 = base + (size_t)rc0 * QKV_N;
        const float* q1 = base + (size_t)rc1 * QKV_N;

        // Q A-fragments straight from gmem (scaled, split)
        uint32_t qh[2][4], ql[2][4];
#pragma unroll
        for (int ks = 0; ks < 2; ks++) {
            const int f0 = ks * 16 + 2 * t4;
            float2 x00 = *(const float2*)(q0 + f0);
            float2 x10 = *(const float2*)(q1 + f0);
            float2 x01 = *(const float2*)(q0 + f0 + 8);
            float2 x11 = *(const float2*)(q1 + f0 + 8);
            x00.x *= QSCALE; x00.y *= QSCALE; x10.x *= QSCALE; x10.y *= QSCALE;
            x01.x *= QSCALE; x01.y *= QSCALE; x11.x *= QSCALE; x11.y *= QSCALE;
            split_pack(x00.x, x00.y, qh[ks][0], ql[ks][0]);
            split_pack(x10.x, x10.y, qh[ks][1], ql[ks][1]);
            split_pack(x01.x, x01.y, qh[ks][2], ql[ks][2]);
            split_pack(x11.x, x11.y, qh[ks][3], ql[ks][3]);
        }

        float c[8][4];
#pragma unroll
        for (int nt = 0; nt < 8; nt++) { c[nt][0] = c[nt][1] = c[nt][2] = c[nt][3] = 0.f; }
#pragma unroll
        for (int nt = 0; nt < 8; nt++) {
            int cn = nt * 8 + gid;
#pragma unroll
            for (int ks = 0; ks < 2; ks++) {
                int cp = ks * 8 + t4;
                uint32_t bh0 = KH[cn * 17 + cp], bh1 = KH[cn * 17 + cp + 4];
                uint32_t bl0 = KL[cn * 17 + cp], bl1 = KL[cn * 17 + cp + 4];
                mma16816(c[nt], qh[ks][0], qh[ks][1], qh[ks][2], qh[ks][3], bh0, bh1);
                mma16816(c[nt], qh[ks][0], qh[ks][1], qh[ks][2], qh[ks][3], bl0, bl1);
                mma16816(c[nt], ql[ks][0], ql[ks][1], ql[ks][2], ql[ks][3], bh0, bh1);
            }
        }

        // bias + shift mask + padding mask
        const int i0 = r0, i1 = r0 + 8;
        const int ih0 = rc0 / WS, iw0 = rc0 % WS;
        const int ih1 = rc1 / WS, iw1 = rc1 % WS;
        int hr, wr, rh, rw;
        hr = hbase + ih0; wr = wbase + iw0;
        rh = (hr < 49) ? 0 : ((hr < 53) ? 1 : 2); rw = (wr < 49) ? 0 : ((wr < 53) ? 1 : 2);
        const int rg0 = rh * 3 + rw;
        hr = hbase + ih1; wr = wbase + iw1;
        rh = (hr < 49) ? 0 : ((hr < 53) ? 1 : 2); rw = (wr < 49) ? 0 : ((wr < 53) ? 1 : 2);
        const int rg1 = rh * 3 + rw;
        (void)i0; (void)i1;

#pragma unroll
        for (int nt = 0; nt < 8; nt++) {
#pragma unroll
            for (int jc = 0; jc < 2; jc++) {
                int j = nt * 8 + 2 * t4 + jc;
                if (j < NTOK) {
                    int jh = j / WS, jw = j % WS;
                    int jhr = hbase + jh, jwr = wbase + jw;
                    int rjh = (jhr < 49) ? 0 : ((jhr < 53) ? 1 : 2);
                    int rjw = (jwr < 49) ? 0 : ((jwr < 53) ? 1 : 2);
                    int rgj = rjh * 3 + rjw;
                    float b0 = TBL[(ih0 - jh + 6) * 13 + (iw0 - jw + 6)];
                    float b1 = TBL[(ih1 - jh + 6) * 13 + (iw1 - jw + 6)];
                    if (rg0 != rgj) b0 -= 100.f;
                    if (rg1 != rgj) b1 -= 100.f;
                    c[nt][jc] += b0;
                    c[nt][2 + jc] += b1;
                } else {
                    c[nt][jc] = -1e30f;
                    c[nt][2 + jc] = -1e30f;
                }
            }
        }

        // softmax over t4 quad
        float m0 = -1e30f, m1 = -1e30f;
#pragma unroll
        for (int nt = 0; nt < 8; nt++) {
            m0 = fmaxf(m0, fmaxf(c[nt][0], c[nt][1]));
            m1 = fmaxf(m1, fmaxf(c[nt][2], c[nt][3]));
        }
        m0 = fmaxf(m0, __shfl_xor_sync(0xffffffffu, m0, 1));
        m0 = fmaxf(m0, __shfl_xor_sync(0xffffffffu, m0, 2));
        m1 = fmaxf(m1, __shfl_xor_sync(0xffffffffu, m1, 1));
        m1 = fmaxf(m1, __shfl_xor_sync(0xffffffffu, m1, 2));
        float s0 = 0.f, s1 = 0.f;
#pragma unroll
        for (int nt = 0; nt < 8; nt++) {
            c[nt][0] = __expf(c[nt][0] - m0); s0 += c[nt][0];
            c[nt][1] = __expf(c[nt][1] - m0); s0 += c[nt][1];
            c[nt][2] = __expf(c[nt][2] - m1); s1 += c[nt][2];
            c[nt][3] = __expf(c[nt][3] - m1); s1 += c[nt][3];
        }
        s0 += __shfl_xor_sync(0xffffffffu, s0, 1);
        s0 += __shfl_xor_sync(0xffffffffu, s0, 2);
        s1 += __shfl_xor_sync(0xffffffffu, s1, 1);
        s1 += __shfl_xor_sync(0xffffffffu, s1, 2);
        const float inv0 = 1.f / s0, inv1 = 1.f / s1;
#pragma unroll
        for (int nt = 0; nt < 8; nt++) {
            c[nt][0] *= inv0; c[nt][1] *= inv0;
            c[nt][2] *= inv1; c[nt][3] *= inv1;
        }

        // O += P V
#pragma unroll
        for (int kt = 0; kt < 4; kt++) {
            uint32_t ph[4], pl[4];
            split_pack(c[2 * kt][0],     c[2 * kt][1],     ph[0], pl[0]);
            split_pack(c[2 * kt][2],     c[2 * kt][3],     ph[1], pl[1]);
            split_pack(c[2 * kt + 1][0], c[2 * kt + 1][1], ph[2], pl[2]);
            split_pack(c[2 * kt + 1][2], c[2 * kt + 1][3], ph[3], pl[3]);
#pragma unroll
            for (int nt = 0; nt < 4; nt++) {
                int dn = nt * 8 + gid;
                uint32_t bh0 = VTH[dn * 33 + kt * 8 + t4];
                uint32_t bh1 = VTH[dn * 33 + kt * 8 + t4 + 4];
                uint32_t bl0 = VTL[dn * 33 + kt * 8 + t4];
                uint32_t bl1 = VTL[dn * 33 + kt * 8 + t4 + 4];
                mma16816(o[mt][nt], ph[0], ph[1], ph[2], ph[3], bh0, bh1);
                mma16816(o[mt][nt], ph[0], ph[1], ph[2], ph[3], bl0, bl1);
                mma16816(o[mt][nt], pl[0], pl[1], pl[2], pl[3], bh0, bh1);
            }
        }
    }

    // store O
#pragma unroll
    for (int mt = 0; mt < 4; mt++) {
        int i0 = mt * 16 + gid, i1 = i0 + 8;
#pragma unroll
        for (int nt = 0; nt < 4; nt++) {
            int d = nt * 8 + 2 * t4;
            if (i0 < NTOK) {
                float2 r; r.x = o[mt][nt][0]; r.y = o[mt][nt][1];
                *(float2*)(out + ((size_t)win * NTOK + i0) * CH + head * HD + d) = r;
            }
            if (i1 < NTOK) {
                float2 r; r.x = o[mt][nt][2]; r.y = o[mt][nt][3];
                *(float2*)(out + ((size_t)win * NTOK + i1) * CH + head * HD + d) = r;
            }
        }
    }
}

extern "C" void kernel_launch(void* const* d_in, const int* in_sizes, int n_in,
                              void* d_out, int out_size) {
    const float* x      = (const float*)d_in[0];
    const float* qkv_w  = (const float*)d_in[1];
    const float* qkv_b  = (const float*)d_in[2];
    const float* proj_w = (const float*)d_in[3];
    const float* proj_b = (const float*)d_in[4];
    const float* table  = (const float*)d_in[5];
    float* out = (float*)d_out;

    float* qkv_buf;
    float* attn_buf;
    cudaGetSymbolAddress((void**)&qkv_buf, g_qkv);
    cudaGetSymbolAddress((void**)&attn_buf, g_attnout);

    cudaFuncSetAttribute(tc_gemm<0>, cudaFuncAttributeMaxDynamicSharedMemorySize, SMEM_GEMM);
    cudaFuncSetAttribute(tc_gemm<1>, cudaFuncAttributeMaxDynamicSharedMemorySize, SMEM_GEMM);

    dim3 g1(QKV_N / 256, M_TOTAL / 128);   // (3, 1568)
    tc_gemm<0><<<g1, 512, SMEM_GEMM>>>(x, qkv_w, qkv_b, qkv_buf);

    attn_mma_kernel<<<BATCH * NWIN * NHEAD, 32>>>(qkv_buf, table, attn_buf);

    dim3 g3(CH / 256, M_TOTAL / 128);      // (1, 1568)
    tc_gemm<1><<<g3, 512, SMEM_GEMM>>>(attn_buf, proj_w, proj_b, out);
}